// round 10
// baseline (speedup 1.0000x reference)
#include <cuda_runtime.h>
#include <cuda_fp16.h>
#include <cstdint>

// ---------------- problem dims ----------------
#define NB 64      // batch
#define ND 512     // input dim
#define NH 1024    // hidden
#define NS 512     // seq len
#define NGP 4096   // packed gate columns (4*H)
#define NCTA 128
#define NTHR 256

// ---------------- lstm_main smem layout ----------------
// per-warp private A chunk: 32 rows x (256+8) halves
#define CH2 264
#define CHB (32 * CH2 * 2)               // 16896 bytes per warp
#define OFF_P (8 * CHB)                  // 135168
#define PLSTR 33                         // floats per lane slot (32 idx + pad)
#define PWSZ (32 * PLSTR)                // 1056 floats per warp partial buf
#define SMEM_MAIN (OFF_P + 8 * PWSZ * 4) // 135168 + 33792 = 168960

// ---------------- xproj smem layout ----------------
#define XSTR 72                          // halves per row (64 + 8 pad)
#define XAB (128 * XSTR * 2)             // 18432 per buffer
#define SMEM_XP (4 * XAB)                // 73728: A0,A1,B0,B1

// ---------------- device scratch (static; no runtime alloc) ----------------
__device__ __half d_Wh[(size_t)NGP * NH];            // packed Wh [p][k], 8.4 MB
__device__ __half d_Wx[(size_t)NGP * ND];            // packed Wx [p][k], 4.2 MB
__device__ float d_bias[NGP];
__device__ __half d_Xh[(size_t)NS * NB * ND];        // x [s][b][d] fp16
__device__ __half d_XP[(size_t)NS * NB * NGP];       // x_proj [s*64+b][p] fp16
__device__ __half d_Hst[(size_t)(NS + 1) * NB * NH]; // H history [t][b][h]
__device__ unsigned d_flag[NCTA];                    // per-CTA step flags

// ---------------- helpers ----------------
static __device__ __forceinline__ unsigned sptr(const void* p) {
    return (unsigned)__cvta_generic_to_shared(p);
}
static __device__ __forceinline__ void cpasync16(unsigned dst, const void* src) {
    asm volatile("cp.async.cg.shared.global [%0], [%1], 16;" ::"r"(dst), "l"(src));
}
static __device__ __forceinline__ void cpcommit() {
    asm volatile("cp.async.commit_group;");
}
static __device__ __forceinline__ void cpwait0() {
    asm volatile("cp.async.wait_group 0;");
}
static __device__ __forceinline__ void cpwait1() {
    asm volatile("cp.async.wait_group 1;");
}
static __device__ __forceinline__ void ldsm4(unsigned& r0, unsigned& r1, unsigned& r2,
                                             unsigned& r3, unsigned addr) {
    asm volatile("ldmatrix.sync.aligned.m8n8.x4.shared.b16 {%0,%1,%2,%3}, [%4];"
                 : "=r"(r0), "=r"(r1), "=r"(r2), "=r"(r3)
                 : "r"(addr));
}
static __device__ __forceinline__ void mma16816(float* d, unsigned a0, unsigned a1,
                                                unsigned a2, unsigned a3,
                                                unsigned b0, unsigned b1) {
    asm volatile(
        "mma.sync.aligned.m16n8k16.row.col.f32.f16.f16.f32 "
        "{%0,%1,%2,%3}, {%4,%5,%6,%7}, {%8,%9}, {%0,%1,%2,%3};"
        : "+f"(d[0]), "+f"(d[1]), "+f"(d[2]), "+f"(d[3])
        : "r"(a0), "r"(a1), "r"(a2), "r"(a3), "r"(b0), "r"(b1));
}
static __device__ __forceinline__ float sigmoidf_(float x) {
    return 1.0f / (1.0f + __expf(-x));
}

// ---------------- pack weights (transpose to [p][k], fp16) + bias + flags ----
__global__ void k_pack(const float* __restrict__ Wxi, const float* __restrict__ Whi,
                       const float* __restrict__ bi, const float* __restrict__ Wxf,
                       const float* __restrict__ Whf, const float* __restrict__ bf_,
                       const float* __restrict__ Wxo, const float* __restrict__ Who,
                       const float* __restrict__ bo, const float* __restrict__ Wxc,
                       const float* __restrict__ Whc, const float* __restrict__ bc) {
    const float* Wx[4] = {Wxi, Wxf, Wxo, Wxc};
    const float* Wh[4] = {Whi, Whf, Who, Whc};
    const float* bb[4] = {bi, bf_, bo, bc};
    size_t i = (size_t)blockIdx.x * blockDim.x + threadIdx.x;
    size_t stride = (size_t)gridDim.x * blockDim.x;
    if (i < NCTA) d_flag[i] = 0u;
    for (size_t idx = i; idx < (size_t)NGP * NH; idx += stride) {
        int k = (int)(idx % NH);
        int p = (int)(idx / NH);
        d_Wh[idx] = __float2half(Wh[p & 3][(size_t)k * NH + (p >> 2)]);
    }
    for (size_t idx = i; idx < (size_t)NGP * ND; idx += stride) {
        int k = (int)(idx % ND);
        int p = (int)(idx / ND);
        d_Wx[idx] = __float2half(Wx[p & 3][(size_t)k * NH + (p >> 2)]);
    }
    for (size_t idx = i; idx < (size_t)NGP; idx += stride) {
        d_bias[idx] = bb[idx & 3][idx >> 2];
    }
}

// ---------------- prep: x -> [s][b][d] fp16; H0 -> Hst[0] --------------------
__global__ void k_prep(const float* __restrict__ x, const float* __restrict__ H0) {
    size_t i = (size_t)blockIdx.x * blockDim.x + threadIdx.x;
    size_t stride = (size_t)gridDim.x * blockDim.x;
    for (size_t idx = i; idx < (size_t)NS * NB * ND; idx += stride) {
        size_t d = idx % ND;
        size_t sb = idx / ND;
        size_t b = sb % NB;
        size_t s = sb / NB;
        d_Xh[idx] = __float2half(x[(b * NS + s) * ND + d]);
    }
    for (size_t idx = i; idx < (size_t)NB * NH; idx += stride) {
        d_Hst[idx] = __float2half(H0[idx]);
    }
}

// ---------------- xproj GEMM: XP[m][p] = sum_d Xh[m][d] * Wx[p][d] -----------
// M=32768, N=4096, K=512. BM=128, BN=128, BK=64, 8 warps @ 32x64, ldmatrix.
__global__ void __launch_bounds__(NTHR, 1) k_xproj() {
    extern __shared__ __align__(16) char sm[];
    const int tid = threadIdx.x;
    const int lane = tid & 31;
    const int wid = tid >> 5;
    const int bx = blockIdx.x;  // m-tile (0..255)
    const int by = blockIdx.y;  // n-tile (0..31)

    const int mbase = (wid >> 1) * 32;
    const int nbase = (wid & 1) * 64;
    const int ra = lane >> 2;
    const int ca = (lane & 3) * 2;

    const __half* Asrc = d_Xh + (size_t)(bx * 128) * ND;
    const __half* Bsrc = d_Wx + (size_t)(by * 128) * ND;

    auto load = [&](int kc) {
        char* Ab = sm + (kc & 1) * XAB;
        char* Bb = sm + 2 * XAB + (kc & 1) * XAB;
#pragma unroll
        for (int j = 0; j < 4; ++j) {
            int q = tid + NTHR * j;
            int row = q >> 3;
            int seg = q & 7;
            cpasync16(sptr(Ab + (row * XSTR + seg * 8) * 2),
                      Asrc + (size_t)row * ND + kc * 64 + seg * 8);
        }
#pragma unroll
        for (int j = 0; j < 4; ++j) {
            int q = tid + NTHR * j;
            int row = q >> 3;
            int seg = q & 7;
            cpasync16(sptr(Bb + (row * XSTR + seg * 8) * 2),
                      Bsrc + (size_t)row * ND + kc * 64 + seg * 8);
        }
        cpcommit();
    };

    float acc[2][8][4];
#pragma unroll
    for (int mi = 0; mi < 2; ++mi)
#pragma unroll
        for (int n8 = 0; n8 < 8; ++n8)
#pragma unroll
            for (int t = 0; t < 4; ++t) acc[mi][n8][t] = 0.f;

    // ldmatrix lane row/col statics
    const int lr = (lane & 7) + ((lane >> 3) & 1) * 8;
    const int lc = (lane >> 4) * 8;

    load(0);
#pragma unroll 1
    for (int kc = 0; kc < 8; ++kc) {
        if (kc < 7) load(kc + 1);
        if (kc < 7) cpwait1();
        else cpwait0();
        __syncthreads();
        const unsigned Abs = sptr(sm + (kc & 1) * XAB);
        const unsigned Bbs = sptr(sm + 2 * XAB + (kc & 1) * XAB);
#pragma unroll
        for (int k16 = 0; k16 < 4; ++k16) {
            unsigned a[2][4];
#pragma unroll
            for (int mi = 0; mi < 2; ++mi) {
                unsigned addr = Abs + (unsigned)(((mbase + mi * 16 + lr) * XSTR + k16 * 16 + lc) * 2);
                ldsm4(a[mi][0], a[mi][1], a[mi][2], a[mi][3], addr);
            }
#pragma unroll
            for (int np = 0; np < 4; ++np) {
                unsigned r0, r1, r2, r3;
                unsigned addr = Bbs + (unsigned)(((nbase + np * 16 + lr) * XSTR + k16 * 16 + lc) * 2);
                ldsm4(r0, r1, r2, r3, addr);
#pragma unroll
                for (int mi = 0; mi < 2; ++mi) {
                    mma16816(acc[mi][2 * np], a[mi][0], a[mi][1], a[mi][2], a[mi][3], r0, r2);
                    mma16816(acc[mi][2 * np + 1], a[mi][0], a[mi][1], a[mi][2], a[mi][3], r1, r3);
                }
            }
        }
        __syncthreads();
    }

#pragma unroll
    for (int mi = 0; mi < 2; ++mi) {
#pragma unroll
        for (int n8 = 0; n8 < 8; ++n8) {
            int m0 = bx * 128 + mbase + mi * 16 + ra;
            int c0 = by * 128 + nbase + n8 * 8 + ca;
            *(__half2*)(d_XP + (size_t)m0 * NGP + c0) =
                __floats2half2_rn(acc[mi][n8][0], acc[mi][n8][1]);
            *(__half2*)(d_XP + (size_t)(m0 + 8) * NGP + c0) =
                __floats2half2_rn(acc[mi][n8][2], acc[mi][n8][3]);
        }
    }
}

// ---------------- persistent LSTM recurrence ----------------
// 128 CTAs x 256 thr. CTA owns 32 packed cols (8 hidden units). K=1024 (H only).
// Warp (kq, mg): kq = wid>>1 (K-slice of 256), mg = wid&1 (M rows mg*32..+32).
// B fragments register-resident (128 regs/thread). 4-way K reduction via smem.
__global__ void __launch_bounds__(NTHR, 1) lstm_main(const float* __restrict__ C0,
                                                     float* __restrict__ out) {
    extern __shared__ __align__(16) char sm[];
    const int tid = threadIdx.x;
    const int lane = tid & 31;
    const int wid = tid >> 5;
    const int kq = wid >> 1;   // 0..3
    const int mg = wid & 1;    // 0..1
    const int cta = blockIdx.x;
    const int pbase = cta * 32;
    const int hbase = cta * 8;
    const int ra = lane >> 2;
    const int ca = (lane & 3) * 2;

    // ---- B fragments (once): n8 0..3, k16 0..15 over K-slice kq*256 ----
    unsigned Bf[4][16][2];
#pragma unroll
    for (int n8 = 0; n8 < 4; ++n8) {
        const __half* wp = d_Wh + (size_t)(pbase + n8 * 8 + ra) * NH + kq * 256 + ca;
#pragma unroll
        for (int k16 = 0; k16 < 16; ++k16) {
            Bf[n8][k16][0] = *(const unsigned*)(wp + k16 * 16);
            Bf[n8][k16][1] = *(const unsigned*)(wp + k16 * 16 + 8);
        }
    }

    // ---- gate-thread identity: (b, 2 hidden units) ----
    const int gb = tid & 63;
    const int gh2 = (tid >> 6) * 2;
    float bias8[8];
#pragma unroll
    for (int j = 0; j < 8; ++j) bias8[j] = d_bias[pbase + gh2 * 4 + j];
    float Creg0 = C0[(size_t)gb * NH + hbase + gh2];
    float Creg1 = C0[(size_t)gb * NH + hbase + gh2 + 1];

    // gather offsets: partial of output (gb, n) from warp (kq, mg_g)
    int goff[8];
    {
        const int mg_g = gb >> 5;
        const int mi = (gb >> 4) & 1;
        const int rh = (gb >> 3) & 1;
        const int raj = gb & 7;
#pragma unroll
        for (int j = 0; j < 8; ++j) {
            int n = gh2 * 4 + j;
            int n8 = n >> 3;
            int lane_j = raj * 4 + ((n & 7) >> 1);
            int idx = (mi * 4 + n8) * 4 + rh * 2 + (n & 1);
            goff[j] = mg_g * PWSZ + lane_j * PLSTR + idx;
        }
    }

    char* mych = sm + wid * CHB;
    const unsigned chs = sptr(mych);
    float* Pbuf = (float*)(sm + OFF_P);
    float* pw = Pbuf + wid * PWSZ + lane * PLSTR;

    // ldmatrix lane statics for A chunk
    const int lr = (lane & 7) + ((lane >> 3) & 1) * 8;
    const unsigned abase = chs + (unsigned)((lr * CH2 + (lane >> 4) * 8) * 2);

    float* outHf = out + (size_t)NB * NS;
    float* outCf = outHf + (size_t)NB * NH;

    volatile unsigned* vflag = (volatile unsigned*)d_flag;

    for (int s = 0; s < NS; ++s) {
        // XP prefetch (independent of H) before the barrier
        uint4 xr = *(const uint4*)(d_XP + ((size_t)s * NB + gb) * NGP + pbase + gh2 * 4);

        if (s > 0) {
            if (tid < NCTA) {
                while (vflag[tid] < (unsigned)s) {
                }
                __threadfence();
            }
            __syncthreads();
        }

        // ---- per-warp load of its 32 rows x 256 halves of H_s, 2 groups ----
        const __half* src = d_Hst + (size_t)s * NB * NH + (size_t)(mg * 32) * NH + kq * 256;
#pragma unroll
        for (int t = 0; t < 16; ++t)
            cpasync16(chs + (unsigned)((t * CH2 + lane * 8) * 2),
                      src + (size_t)t * NH + lane * 8);
        cpcommit();
#pragma unroll
        for (int t = 16; t < 32; ++t)
            cpasync16(chs + (unsigned)((t * CH2 + lane * 8) * 2),
                      src + (size_t)t * NH + lane * 8);
        cpcommit();

        float acc[2][4][4];
#pragma unroll
        for (int mi = 0; mi < 2; ++mi)
#pragma unroll
            for (int n8 = 0; n8 < 4; ++n8)
#pragma unroll
                for (int t = 0; t < 4; ++t) acc[mi][n8][t] = 0.f;

        cpwait1();  // rows 0..15 ready
#pragma unroll
        for (int k16 = 0; k16 < 16; ++k16) {
            unsigned a0, a1, a2, a3;
            ldsm4(a0, a1, a2, a3, abase + (unsigned)(k16 * 32));
#pragma unroll
            for (int n8 = 0; n8 < 4; ++n8)
                mma16816(acc[0][n8], a0, a1, a2, a3, Bf[n8][k16][0], Bf[n8][k16][1]);
        }
        cpwait0();  // rows 16..31 ready
#pragma unroll
        for (int k16 = 0; k16 < 16; ++k16) {
            unsigned a0, a1, a2, a3;
            ldsm4(a0, a1, a2, a3, abase + (unsigned)((16 * CH2 + k16 * 16) * 2));
#pragma unroll
            for (int n8 = 0; n8 < 4; ++n8)
                mma16816(acc[1][n8], a0, a1, a2, a3, Bf[n8][k16][0], Bf[n8][k16][1]);
        }

        // ---- write partials (conflict-free: (lane + idx) % 32 distinct) ----
#pragma unroll
        for (int mi = 0; mi < 2; ++mi)
#pragma unroll
            for (int n8 = 0; n8 < 4; ++n8)
#pragma unroll
                for (int t = 0; t < 4; ++t)
                    pw[(mi * 4 + n8) * 4 + t] = acc[mi][n8][t];
        __syncthreads();

        // ---- 4-way K reduction + x_proj + gates ----
        {
            float g[8];
#pragma unroll
            for (int j = 0; j < 8; ++j) {
                float v = 0.f;
#pragma unroll
                for (int q = 0; q < 4; ++q) v += Pbuf[q * (2 * PWSZ) + goff[j]];
                g[j] = v;
            }
            const __half2* xh = (const __half2*)&xr;
            float xv[8];
#pragma unroll
            for (int t = 0; t < 4; ++t) {
                xv[2 * t] = __low2float(xh[t]);
                xv[2 * t + 1] = __high2float(xh[t]);
            }
            float hn0, hn1, cn0, cn1;
            {
                float gi = g[0] + bias8[0] + xv[0];
                float gf = g[1] + bias8[1] + xv[1];
                float go = g[2] + bias8[2] + xv[2];
                float gc = g[3] + bias8[3] + xv[3];
                float iv = sigmoidf_(gi), fv = sigmoidf_(gf);
                float ov = sigmoidf_(go), cv = tanhf(gc);
                cn0 = fv * Creg0 + iv * cv;
                hn0 = ov * tanhf(cn0);
                Creg0 = cn0;
            }
            {
                float gi = g[4] + bias8[4] + xv[4];
                float gf = g[5] + bias8[5] + xv[5];
                float go = g[6] + bias8[6] + xv[6];
                float gc = g[7] + bias8[7] + xv[7];
                float iv = sigmoidf_(gi), fv = sigmoidf_(gf);
                float ov = sigmoidf_(go), cv = tanhf(gc);
                cn1 = fv * Creg1 + iv * cv;
                hn1 = ov * tanhf(cn1);
                Creg1 = cn1;
            }
            *(__half2*)(d_Hst + (size_t)(s + 1) * NB * NH + (size_t)gb * NH + hbase + gh2) =
                __floats2half2_rn(hn0, hn1);
            if (s == NS - 1) {
                outHf[(size_t)gb * NH + hbase + gh2] = hn0;
                outHf[(size_t)gb * NH + hbase + gh2 + 1] = hn1;
                outCf[(size_t)gb * NH + hbase + gh2] = cn0;
                outCf[(size_t)gb * NH + hbase + gh2 + 1] = cn1;
            }
        }

        __threadfence();
        __syncthreads();
        if (tid == 0) vflag[cta] = (unsigned)(s + 1);
    }
}

// ---------------- final GEMV: pred[b][s] ----------------
__global__ void k_pred(const float* __restrict__ fcW, const float* __restrict__ fcb,
                       float* __restrict__ out) {
    const int w = blockIdx.x * (blockDim.x >> 5) + (threadIdx.x >> 5);
    const int lane = threadIdx.x & 31;
    const int b = w >> 9;
    const int s = w & 511;
    const __half2* hp = (const __half2*)(d_Hst + (size_t)(s + 1) * NB * NH + (size_t)b * NH);
    const float2* wp = (const float2*)fcW;
    float acc = 0.f;
#pragma unroll 4
    for (int j = lane; j < NH / 2; j += 32) {
        __half2 h2 = hp[j];
        float2 wv = wp[j];
        acc += __low2float(h2) * wv.x + __high2float(h2) * wv.y;
    }
#pragma unroll
    for (int o = 16; o; o >>= 1) acc += __shfl_xor_sync(0xffffffffu, acc, o);
    if (lane == 0) out[(size_t)b * NS + s] = acc + fcb[0];
}

// ---------------- launch ----------------
extern "C" void kernel_launch(void* const* d_in, const int* in_sizes, int n_in,
                              void* d_out, int out_size) {
    (void)in_sizes;
    (void)n_in;
    (void)out_size;
    const float* x = (const float*)d_in[0];
    const float* H0 = (const float*)d_in[1];
    const float* C0 = (const float*)d_in[2];
    const float* Wxi = (const float*)d_in[3];
    const float* Whi = (const float*)d_in[4];
    const float* bi = (const float*)d_in[5];
    const float* Wxf = (const float*)d_in[6];
    const float* Whf = (const float*)d_in[7];
    const float* bf_ = (const float*)d_in[8];
    const float* Wxo = (const float*)d_in[9];
    const float* Who = (const float*)d_in[10];
    const float* bo = (const float*)d_in[11];
    const float* Wxc = (const float*)d_in[12];
    const float* Whc = (const float*)d_in[13];
    const float* bc = (const float*)d_in[14];
    const float* fcW = (const float*)d_in[15];
    const float* fcb = (const float*)d_in[16];
    float* out = (float*)d_out;

    cudaFuncSetAttribute(lstm_main, cudaFuncAttributeMaxDynamicSharedMemorySize, SMEM_MAIN);
    cudaFuncSetAttribute(k_xproj, cudaFuncAttributeMaxDynamicSharedMemorySize, SMEM_XP);

    k_pack<<<2048, 256>>>(Wxi, Whi, bi, Wxf, Whf, bf_, Wxo, Who, bo, Wxc, Whc, bc);
    k_prep<<<4096, 256>>>(x, H0);
    {
        dim3 g(256, 32);
        k_xproj<<<g, NTHR, SMEM_XP>>>();
    }
    lstm_main<<<NCTA, NTHR, SMEM_MAIN>>>(C0, out);
    k_pred<<<4096, 256>>>(fcW, fcb, out);
}

// round 11
// speedup vs baseline: 1.2776x; 1.2776x over previous
#include <cuda_runtime.h>
#include <cuda_fp16.h>
#include <cstdint>

// ---------------- problem dims ----------------
#define NB 64      // batch
#define ND 512     // input dim
#define NH 1024    // hidden
#define NS 512     // seq len
#define NGP 4096   // packed gate columns (4*H)
#define NCTA 128
#define NTHR 256

// ---------------- lstm_main smem layout (R9-proven) ----------------
#define CHSTR 136                        // halves per A row (128 + 8 pad)
#define CHB (64 * CHSTR * 2)             // 17408 bytes per warp chunk
#define OFF_P (8 * CHB)                  // 139264
#define PWSTR 65                         // floats per lane slot
#define PWFL (32 * PWSTR)                // 2080 floats per warp partial buf
#define SMEM_MAIN (OFF_P + 8 * PWFL * 4) // 205824 bytes

// ---------------- xproj smem layout ----------------
#define XSTR 72                          // halves per row (64 + 8 pad)
#define XAB (128 * XSTR * 2)             // 18432 per buffer
#define SMEM_XP (4 * XAB)                // 73728: A0,A1,B0,B1

// ---------------- device scratch (static; no runtime alloc) ----------------
__device__ __half d_Wh[(size_t)NGP * NH];            // packed Wh [p][k]
__device__ __half d_Wx[(size_t)NGP * ND];            // packed Wx [p][k]
__device__ float d_bias[NGP];
__device__ __half d_Xh[(size_t)NS * NB * ND];        // x [s][b][d] fp16
__device__ __half d_XP[(size_t)NS * NB * NGP];       // x_proj [s*64+b][p] fp16
__device__ __half d_Hst[(size_t)(NS + 1) * NB * NH]; // H history [t][b][h]
__device__ unsigned d_cnt[NS * 8];                   // per-(step, kq-group) counters

// ---------------- helpers ----------------
static __device__ __forceinline__ unsigned sptr(const void* p) {
    return (unsigned)__cvta_generic_to_shared(p);
}
static __device__ __forceinline__ void cpasync16(unsigned dst, const void* src) {
    asm volatile("cp.async.cg.shared.global [%0], [%1], 16;" ::"r"(dst), "l"(src));
}
static __device__ __forceinline__ void cpcommit() {
    asm volatile("cp.async.commit_group;");
}
static __device__ __forceinline__ void cpwait0() {
    asm volatile("cp.async.wait_group 0;");
}
static __device__ __forceinline__ void cpwait1() {
    asm volatile("cp.async.wait_group 1;");
}
static __device__ __forceinline__ void ldsm4(unsigned& r0, unsigned& r1, unsigned& r2,
                                             unsigned& r3, unsigned addr) {
    asm volatile("ldmatrix.sync.aligned.m8n8.x4.shared.b16 {%0,%1,%2,%3}, [%4];"
                 : "=r"(r0), "=r"(r1), "=r"(r2), "=r"(r3)
                 : "r"(addr));
}
static __device__ __forceinline__ void mma16816(float* d, unsigned a0, unsigned a1,
                                                unsigned a2, unsigned a3,
                                                unsigned b0, unsigned b1) {
    asm volatile(
        "mma.sync.aligned.m16n8k16.row.col.f32.f16.f16.f32 "
        "{%0,%1,%2,%3}, {%4,%5,%6,%7}, {%8,%9}, {%0,%1,%2,%3};"
        : "+f"(d[0]), "+f"(d[1]), "+f"(d[2]), "+f"(d[3])
        : "r"(a0), "r"(a1), "r"(a2), "r"(a3), "r"(b0), "r"(b1));
}
static __device__ __forceinline__ float sigmoidf_(float x) {
    return 1.0f / (1.0f + __expf(-x));
}

// ---------------- pack weights (transpose to [p][k], fp16) + bias + cnt ------
__global__ void k_pack(const float* __restrict__ Wxi, const float* __restrict__ Whi,
                       const float* __restrict__ bi, const float* __restrict__ Wxf,
                       const float* __restrict__ Whf, const float* __restrict__ bf_,
                       const float* __restrict__ Wxo, const float* __restrict__ Who,
                       const float* __restrict__ bo, const float* __restrict__ Wxc,
                       const float* __restrict__ Whc, const float* __restrict__ bc) {
    const float* Wx[4] = {Wxi, Wxf, Wxo, Wxc};
    const float* Wh[4] = {Whi, Whf, Who, Whc};
    const float* bb[4] = {bi, bf_, bo, bc};
    size_t i = (size_t)blockIdx.x * blockDim.x + threadIdx.x;
    size_t stride = (size_t)gridDim.x * blockDim.x;
    for (size_t idx = i; idx < (size_t)NS * 8; idx += stride) d_cnt[idx] = 0u;
    for (size_t idx = i; idx < (size_t)NGP * NH; idx += stride) {
        int k = (int)(idx % NH);
        int p = (int)(idx / NH);
        d_Wh[idx] = __float2half(Wh[p & 3][(size_t)k * NH + (p >> 2)]);
    }
    for (size_t idx = i; idx < (size_t)NGP * ND; idx += stride) {
        int k = (int)(idx % ND);
        int p = (int)(idx / ND);
        d_Wx[idx] = __float2half(Wx[p & 3][(size_t)k * NH + (p >> 2)]);
    }
    for (size_t idx = i; idx < (size_t)NGP; idx += stride) {
        d_bias[idx] = bb[idx & 3][idx >> 2];
    }
}

// ---------------- prep: x -> [s][b][d] fp16; H0 -> Hst[0] --------------------
__global__ void k_prep(const float* __restrict__ x, const float* __restrict__ H0) {
    size_t i = (size_t)blockIdx.x * blockDim.x + threadIdx.x;
    size_t stride = (size_t)gridDim.x * blockDim.x;
    for (size_t idx = i; idx < (size_t)NS * NB * ND; idx += stride) {
        size_t d = idx % ND;
        size_t sb = idx / ND;
        size_t b = sb % NB;
        size_t s = sb / NB;
        d_Xh[idx] = __float2half(x[(b * NS + s) * ND + d]);
    }
    for (size_t idx = i; idx < (size_t)NB * NH; idx += stride) {
        d_Hst[idx] = __float2half(H0[idx]);
    }
}

// ---------------- xproj GEMM: XP[m][p] = sum_d Xh[m][d] * Wx[p][d] -----------
// M=32768, N=4096, K=512. BM=128, BN=128, BK=64, 8 warps @ 32x64, ldmatrix.
__global__ void __launch_bounds__(NTHR, 1) k_xproj() {
    extern __shared__ __align__(16) char sm[];
    const int tid = threadIdx.x;
    const int lane = tid & 31;
    const int wid = tid >> 5;
    const int bx = blockIdx.x;  // m-tile
    const int by = blockIdx.y;  // n-tile

    const int mbase = (wid >> 1) * 32;
    const int nbase = (wid & 1) * 64;
    const int ra = lane >> 2;
    const int ca = (lane & 3) * 2;

    const __half* Asrc = d_Xh + (size_t)(bx * 128) * ND;
    const __half* Bsrc = d_Wx + (size_t)(by * 128) * ND;

    auto load = [&](int kc) {
        char* Ab = sm + (kc & 1) * XAB;
        char* Bb = sm + 2 * XAB + (kc & 1) * XAB;
#pragma unroll
        for (int j = 0; j < 4; ++j) {
            int q = tid + NTHR * j;
            int row = q >> 3;
            int seg = q & 7;
            cpasync16(sptr(Ab + (row * XSTR + seg * 8) * 2),
                      Asrc + (size_t)row * ND + kc * 64 + seg * 8);
        }
#pragma unroll
        for (int j = 0; j < 4; ++j) {
            int q = tid + NTHR * j;
            int row = q >> 3;
            int seg = q & 7;
            cpasync16(sptr(Bb + (row * XSTR + seg * 8) * 2),
                      Bsrc + (size_t)row * ND + kc * 64 + seg * 8);
        }
        cpcommit();
    };

    float acc[2][8][4];
#pragma unroll
    for (int mi = 0; mi < 2; ++mi)
#pragma unroll
        for (int n8 = 0; n8 < 8; ++n8)
#pragma unroll
            for (int t = 0; t < 4; ++t) acc[mi][n8][t] = 0.f;

    const int lr = (lane & 7) + ((lane >> 3) & 1) * 8;
    const int lc = (lane >> 4) * 8;

    load(0);
#pragma unroll 1
    for (int kc = 0; kc < 8; ++kc) {
        if (kc < 7) load(kc + 1);
        if (kc < 7) cpwait1();
        else cpwait0();
        __syncthreads();
        const unsigned Abs = sptr(sm + (kc & 1) * XAB);
        const unsigned Bbs = sptr(sm + 2 * XAB + (kc & 1) * XAB);
#pragma unroll
        for (int k16 = 0; k16 < 4; ++k16) {
            unsigned a[2][4];
#pragma unroll
            for (int mi = 0; mi < 2; ++mi) {
                unsigned addr =
                    Abs + (unsigned)(((mbase + mi * 16 + lr) * XSTR + k16 * 16 + lc) * 2);
                ldsm4(a[mi][0], a[mi][1], a[mi][2], a[mi][3], addr);
            }
#pragma unroll
            for (int np = 0; np < 4; ++np) {
                unsigned r0, r1, r2, r3;
                unsigned addr =
                    Bbs + (unsigned)(((nbase + np * 16 + lr) * XSTR + k16 * 16 + lc) * 2);
                ldsm4(r0, r1, r2, r3, addr);
#pragma unroll
                for (int mi = 0; mi < 2; ++mi) {
                    mma16816(acc[mi][2 * np], a[mi][0], a[mi][1], a[mi][2], a[mi][3], r0, r2);
                    mma16816(acc[mi][2 * np + 1], a[mi][0], a[mi][1], a[mi][2], a[mi][3], r1, r3);
                }
            }
        }
        __syncthreads();
    }

#pragma unroll
    for (int mi = 0; mi < 2; ++mi) {
#pragma unroll
        for (int n8 = 0; n8 < 8; ++n8) {
            int m0 = bx * 128 + mbase + mi * 16 + ra;
            int c0 = by * 128 + nbase + n8 * 8 + ca;
            *(__half2*)(d_XP + (size_t)m0 * NGP + c0) =
                __floats2half2_rn(acc[mi][n8][0], acc[mi][n8][1]);
            *(__half2*)(d_XP + (size_t)(m0 + 8) * NGP + c0) =
                __floats2half2_rn(acc[mi][n8][2], acc[mi][n8][3]);
        }
    }
}

// ---------------- persistent LSTM recurrence (dataflow-synced) ----------------
// 128 CTAs x 256 thr. CTA owns 32 packed cols (8 hidden units). K=1024.
// Warp kq (0..7) computes 64M x 32N over K slice [kq*128, kq*128+128).
// Slice kq of H_s is produced by CTAs kq*16..kq*16+15; sync via per-(s, kq)
// release/acquire counters instead of a full grid barrier.
__global__ void __launch_bounds__(NTHR, 1) lstm_main(const float* __restrict__ C0,
                                                     float* __restrict__ out) {
    extern __shared__ __align__(16) char sm[];
    const int tid = threadIdx.x;
    const int lane = tid & 31;
    const int wid = tid >> 5;  // = kq
    const int cta = blockIdx.x;
    const int pbase = cta * 32;
    const int hbase = cta * 8;
    const int ra = lane >> 2;
    const int ca = (lane & 3) * 2;

    // ---- B fragments (once): 64 regs/thread ----
    unsigned Bf[4][8][2];
#pragma unroll
    for (int n8 = 0; n8 < 4; ++n8) {
        const __half* wp = d_Wh + (size_t)(pbase + n8 * 8 + ra) * NH + wid * 128 + ca;
#pragma unroll
        for (int k16 = 0; k16 < 8; ++k16) {
            Bf[n8][k16][0] = *(const unsigned*)(wp + k16 * 16);
            Bf[n8][k16][1] = *(const unsigned*)(wp + k16 * 16 + 8);
        }
    }

    // ---- gate-thread identity: (b, 2 hidden units) ----
    const int gb = tid & 63;
    const int gh2 = (tid >> 6) * 2;
    float bias8[8];
#pragma unroll
    for (int j = 0; j < 8; ++j) bias8[j] = d_bias[pbase + gh2 * 4 + j];
    float Creg0 = C0[(size_t)gb * NH + hbase + gh2];
    float Creg1 = C0[(size_t)gb * NH + hbase + gh2 + 1];

    // gather offsets (R9-proven mapping)
    int sl[8], gi_[8];
#pragma unroll
    for (int j = 0; j < 8; ++j) {
        int n = gh2 * 4 + j;
        sl[j] = (gb & 7) * 4 + ((n >> 1) & 3);
        gi_[j] = ((gb >> 4) * 4 + (n >> 3)) * 4 + ((gb >> 3) & 1) * 2 + (n & 1);
    }

    char* mych = sm + wid * CHB;
    const unsigned chs = sptr(mych);
    float* Pbuf = (float*)(sm + OFF_P);
    float* pw = Pbuf + wid * PWFL + lane * PWSTR;

    // ldmatrix lane statics
    const int lr = (lane & 7) + ((lane >> 3) & 1) * 8;
    const unsigned abase = chs + (unsigned)((lr * CHSTR + (lane >> 4) * 8) * 2);

    float* outHf = out + (size_t)NB * NS;
    float* outCf = outHf + (size_t)NB * NH;

    const unsigned grp = (unsigned)(cta >> 4);

    for (int s = 0; s < NS; ++s) {
        // XP prefetch (independent of H) before any waiting
        uint4 xr = *(const uint4*)(d_XP + ((size_t)s * NB + gb) * NGP + pbase + gh2 * 4);

        // ---- wait for the 16 producers of this warp's K-slice ----
        if (s > 0) {
            const unsigned* cp = &d_cnt[(size_t)s * 8 + wid];
            unsigned v;
            do {
                asm volatile("ld.acquire.gpu.global.u32 %0, [%1];" : "=r"(v) : "l"(cp));
            } while (v < 16u);
            __syncwarp();
        }

        // ---- per-warp load: 64 rows x 128 halves of H_s slice, 2 groups ----
        const __half* src = d_Hst + (size_t)s * NB * NH + wid * 128;
#pragma unroll
        for (int j = 0; j < 16; ++j) {
            int q = j * 32 + lane;
            int row = q >> 4;
            int seg = q & 15;
            cpasync16(chs + (unsigned)((row * CHSTR + seg * 8) * 2),
                      src + (size_t)row * NH + seg * 8);
        }
        cpcommit();
#pragma unroll
        for (int j = 16; j < 32; ++j) {
            int q = j * 32 + lane;
            int row = q >> 4;
            int seg = q & 15;
            cpasync16(chs + (unsigned)((row * CHSTR + seg * 8) * 2),
                      src + (size_t)row * NH + seg * 8);
        }
        cpcommit();

        float acc[4][4][4];
#pragma unroll
        for (int mi = 0; mi < 4; ++mi)
#pragma unroll
            for (int n8 = 0; n8 < 4; ++n8)
#pragma unroll
                for (int t = 0; t < 4; ++t) acc[mi][n8][t] = 0.f;

        cpwait1();  // rows 0..31 ready
#pragma unroll
        for (int mi = 0; mi < 2; ++mi)
#pragma unroll
            for (int k16 = 0; k16 < 8; ++k16) {
                unsigned a0, a1, a2, a3;
                ldsm4(a0, a1, a2, a3,
                      abase + (unsigned)(mi * 16 * CHSTR * 2 + k16 * 32));
#pragma unroll
                for (int n8 = 0; n8 < 4; ++n8)
                    mma16816(acc[mi][n8], a0, a1, a2, a3, Bf[n8][k16][0], Bf[n8][k16][1]);
            }
        cpwait0();  // rows 32..63 ready
#pragma unroll
        for (int mi = 2; mi < 4; ++mi)
#pragma unroll
            for (int k16 = 0; k16 < 8; ++k16) {
                unsigned a0, a1, a2, a3;
                ldsm4(a0, a1, a2, a3,
                      abase + (unsigned)(mi * 16 * CHSTR * 2 + k16 * 32));
#pragma unroll
                for (int n8 = 0; n8 < 4; ++n8)
                    mma16816(acc[mi][n8], a0, a1, a2, a3, Bf[n8][k16][0], Bf[n8][k16][1]);
            }

        // ---- write partials ----
#pragma unroll
        for (int mi = 0; mi < 4; ++mi)
#pragma unroll
            for (int n8 = 0; n8 < 4; ++n8)
#pragma unroll
                for (int t = 0; t < 4; ++t)
                    pw[(mi * 4 + n8) * 4 + t] = acc[mi][n8][t];
        __syncthreads();

        // ---- 8-way K reduction + x_proj + gates ----
        {
            float g[8];
#pragma unroll
            for (int j = 0; j < 8; ++j) {
                float v = 0.f;
                const int off = sl[j] * PWSTR + gi_[j];
#pragma unroll
                for (int w = 0; w < 8; ++w) v += Pbuf[w * PWFL + off];
                g[j] = v;
            }
            const __half2* xh = (const __half2*)&xr;
            float xv[8];
#pragma unroll
            for (int t = 0; t < 4; ++t) {
                xv[2 * t] = __low2float(xh[t]);
                xv[2 * t + 1] = __high2float(xh[t]);
            }
            float hn0, hn1, cn0, cn1;
            {
                float gi = g[0] + bias8[0] + xv[0];
                float gf = g[1] + bias8[1] + xv[1];
                float go = g[2] + bias8[2] + xv[2];
                float gc = g[3] + bias8[3] + xv[3];
                float iv = sigmoidf_(gi), fv = sigmoidf_(gf);
                float ov = sigmoidf_(go), cv = tanhf(gc);
                cn0 = fv * Creg0 + iv * cv;
                hn0 = ov * tanhf(cn0);
                Creg0 = cn0;
            }
            {
                float gi = g[4] + bias8[4] + xv[4];
                float gf = g[5] + bias8[5] + xv[5];
                float go = g[6] + bias8[6] + xv[6];
                float gc = g[7] + bias8[7] + xv[7];
                float iv = sigmoidf_(gi), fv = sigmoidf_(gf);
                float ov = sigmoidf_(go), cv = tanhf(gc);
                cn1 = fv * Creg1 + iv * cv;
                hn1 = ov * tanhf(cn1);
                Creg1 = cn1;
            }
            *(__half2*)(d_Hst + (size_t)(s + 1) * NB * NH + (size_t)gb * NH + hbase + gh2) =
                __floats2half2_rn(hn0, hn1);
            if (s == NS - 1) {
                outHf[(size_t)gb * NH + hbase + gh2] = hn0;
                outHf[(size_t)gb * NH + hbase + gh2 + 1] = hn1;
                outCf[(size_t)gb * NH + hbase + gh2] = cn0;
                outCf[(size_t)gb * NH + hbase + gh2 + 1] = cn1;
            }
        }

        // ---- publish H_{s+1}: fence all threads' stores, then release-inc ----
        __threadfence();
        __syncthreads();  // also guards partial-buffer WAR for next step
        if (tid == 0 && s < NS - 1) {
            const unsigned* cp = &d_cnt[(size_t)(s + 1) * 8 + grp];
            asm volatile("red.release.gpu.global.add.u32 [%0], %1;" ::"l"(cp), "r"(1u));
        }
    }
}

// ---------------- final GEMV: pred[b][s] ----------------
__global__ void k_pred(const float* __restrict__ fcW, const float* __restrict__ fcb,
                       float* __restrict__ out) {
    const int w = blockIdx.x * (blockDim.x >> 5) + (threadIdx.x >> 5);
    const int lane = threadIdx.x & 31;
    const int b = w >> 9;
    const int s = w & 511;
    const __half2* hp = (const __half2*)(d_Hst + (size_t)(s + 1) * NB * NH + (size_t)b * NH);
    const float2* wp = (const float2*)fcW;
    float acc = 0.f;
#pragma unroll 4
    for (int j = lane; j < NH / 2; j += 32) {
        __half2 h2 = hp[j];
        float2 wv = wp[j];
        acc += __low2float(h2) * wv.x + __high2float(h2) * wv.y;
    }
#pragma unroll
    for (int o = 16; o; o >>= 1) acc += __shfl_xor_sync(0xffffffffu, acc, o);
    if (lane == 0) out[(size_t)b * NS + s] = acc + fcb[0];
}

// ---------------- launch ----------------
extern "C" void kernel_launch(void* const* d_in, const int* in_sizes, int n_in,
                              void* d_out, int out_size) {
    (void)in_sizes;
    (void)n_in;
    (void)out_size;
    const float* x = (const float*)d_in[0];
    const float* H0 = (const float*)d_in[1];
    const float* C0 = (const float*)d_in[2];
    const float* Wxi = (const float*)d_in[3];
    const float* Whi = (const float*)d_in[4];
    const float* bi = (const float*)d_in[5];
    const float* Wxf = (const float*)d_in[6];
    const float* Whf = (const float*)d_in[7];
    const float* bf_ = (const float*)d_in[8];
    const float* Wxo = (const float*)d_in[9];
    const float* Who = (const float*)d_in[10];
    const float* bo = (const float*)d_in[11];
    const float* Wxc = (const float*)d_in[12];
    const float* Whc = (const float*)d_in[13];
    const float* bc = (const float*)d_in[14];
    const float* fcW = (const float*)d_in[15];
    const float* fcb = (const float*)d_in[16];
    float* out = (float*)d_out;

    cudaFuncSetAttribute(lstm_main, cudaFuncAttributeMaxDynamicSharedMemorySize, SMEM_MAIN);
    cudaFuncSetAttribute(k_xproj, cudaFuncAttributeMaxDynamicSharedMemorySize, SMEM_XP);

    k_pack<<<2048, 256>>>(Wxi, Whi, bi, Wxf, Whf, bf_, Wxo, Who, bo, Wxc, Whc, bc);
    k_prep<<<4096, 256>>>(x, H0);
    {
        dim3 g(256, 32);
        k_xproj<<<g, NTHR, SMEM_XP>>>();
    }
    lstm_main<<<NCTA, NTHR, SMEM_MAIN>>>(C0, out);
    k_pred<<<4096, 256>>>(fcW, fcb, out);
}

// round 14
// speedup vs baseline: 1.7750x; 1.3893x over previous
#include <cuda_runtime.h>
#include <cuda_fp16.h>
#include <cstdint>

// ---------------- problem dims ----------------
#define NB 64      // batch
#define ND 512     // input dim
#define NH 1024    // hidden
#define NS 512     // seq len
#define NGP 4096   // packed gate columns (4*H)
#define NCTA 128
#define NTHR 256

// ---------------- lstm_main smem layout (R9-proven + XP slab) ----------------
#define CHSTR 136                        // halves per A row (128 + 8 pad)
#define CHB (64 * CHSTR * 2)             // 17408 bytes per warp chunk
#define OFF_P (8 * CHB)                  // 139264
#define PWSTR 65                         // floats per lane slot
#define PWFL (32 * PWSTR)                // 2080 floats per warp partial buf
#define OFF_XP (OFF_P + 8 * PWFL * 4)    // 205824
#define SMEM_MAIN (OFF_XP + 2 * 4096)    // + double-buffered XP slab = 214016

// ---------------- xproj smem layout ----------------
#define XSTR 72                          // halves per row (64 + 8 pad)
#define XAB (128 * XSTR * 2)             // 18432 per buffer
#define SMEM_XP (4 * XAB)                // 73728: A0,A1,B0,B1

// ---------------- device scratch (static; no runtime alloc) ----------------
__device__ __half d_Wh[(size_t)NGP * NH];            // packed Wh [p][k]
__device__ __half d_Wx[(size_t)NGP * ND];            // packed Wx [p][k]
__device__ float d_bias[NGP];
__device__ __half d_Xh[(size_t)NS * NB * ND];        // x [s][b][d] fp16
__device__ __half d_XP[(size_t)NS * NB * NGP];       // x_proj [s*64+b][p] fp16
__device__ __half d_Hst[(size_t)(NS + 1) * NB * NH]; // H history [t][b][h]
__device__ unsigned d_cnt[NS * 8];                   // per-(step, slice) counters

// ---------------- helpers ----------------
static __device__ __forceinline__ unsigned sptr(const void* p) {
    return (unsigned)__cvta_generic_to_shared(p);
}
static __device__ __forceinline__ void cpasync16(unsigned dst, const void* src) {
    asm volatile("cp.async.cg.shared.global [%0], [%1], 16;" ::"r"(dst), "l"(src));
}
static __device__ __forceinline__ void cpcommit() {
    asm volatile("cp.async.commit_group;");
}
static __device__ __forceinline__ void cpwait0() {
    asm volatile("cp.async.wait_group 0;");
}
static __device__ __forceinline__ void cpwait1() {
    asm volatile("cp.async.wait_group 1;");
}
static __device__ __forceinline__ void ldsm4(unsigned& r0, unsigned& r1, unsigned& r2,
                                             unsigned& r3, unsigned addr) {
    asm volatile("ldmatrix.sync.aligned.m8n8.x4.shared.b16 {%0,%1,%2,%3}, [%4];"
                 : "=r"(r0), "=r"(r1), "=r"(r2), "=r"(r3)
                 : "r"(addr));
}
static __device__ __forceinline__ void mma16816(float* d, unsigned a0, unsigned a1,
                                                unsigned a2, unsigned a3,
                                                unsigned b0, unsigned b1) {
    asm volatile(
        "mma.sync.aligned.m16n8k16.row.col.f32.f16.f16.f32 "
        "{%0,%1,%2,%3}, {%4,%5,%6,%7}, {%8,%9}, {%0,%1,%2,%3};"
        : "+f"(d[0]), "+f"(d[1]), "+f"(d[2]), "+f"(d[3])
        : "r"(a0), "r"(a1), "r"(a2), "r"(a3), "r"(b0), "r"(b1));
}
static __device__ __forceinline__ float sigmoidf_(float x) {
    return 1.0f / (1.0f + __expf(-x));
}

// ---------------- pack weights (transpose to [p][k], fp16) + bias + cnt ------
__global__ void k_pack(const float* __restrict__ Wxi, const float* __restrict__ Whi,
                       const float* __restrict__ bi, const float* __restrict__ Wxf,
                       const float* __restrict__ Whf, const float* __restrict__ bf_,
                       const float* __restrict__ Wxo, const float* __restrict__ Who,
                       const float* __restrict__ bo, const float* __restrict__ Wxc,
                       const float* __restrict__ Whc, const float* __restrict__ bc) {
    const float* Wx[4] = {Wxi, Wxf, Wxo, Wxc};
    const float* Wh[4] = {Whi, Whf, Who, Whc};
    const float* bb[4] = {bi, bf_, bo, bc};
    size_t i = (size_t)blockIdx.x * blockDim.x + threadIdx.x;
    size_t stride = (size_t)gridDim.x * blockDim.x;
    for (size_t idx = i; idx < (size_t)NS * 8; idx += stride) d_cnt[idx] = 0u;
    for (size_t idx = i; idx < (size_t)NGP * NH; idx += stride) {
        int k = (int)(idx % NH);
        int p = (int)(idx / NH);
        d_Wh[idx] = __float2half(Wh[p & 3][(size_t)k * NH + (p >> 2)]);
    }
    for (size_t idx = i; idx < (size_t)NGP * ND; idx += stride) {
        int k = (int)(idx % ND);
        int p = (int)(idx / ND);
        d_Wx[idx] = __float2half(Wx[p & 3][(size_t)k * NH + (p >> 2)]);
    }
    for (size_t idx = i; idx < (size_t)NGP; idx += stride) {
        d_bias[idx] = bb[idx & 3][idx >> 2];
    }
}

// ---------------- prep: x -> [s][b][d] fp16; H0 -> Hst[0] --------------------
__global__ void k_prep(const float* __restrict__ x, const float* __restrict__ H0) {
    size_t i = (size_t)blockIdx.x * blockDim.x + threadIdx.x;
    size_t stride = (size_t)gridDim.x * blockDim.x;
    for (size_t idx = i; idx < (size_t)NS * NB * ND; idx += stride) {
        size_t d = idx % ND;
        size_t sb = idx / ND;
        size_t b = sb % NB;
        size_t s = sb / NB;
        d_Xh[idx] = __float2half(x[(b * NS + s) * ND + d]);
    }
    for (size_t idx = i; idx < (size_t)NB * NH; idx += stride) {
        d_Hst[idx] = __float2half(H0[idx]);
    }
}

// ---------------- xproj GEMM: XP[m][p] = sum_d Xh[m][d] * Wx[p][d] -----------
// M=32768, N=4096, K=512. BM=128, BN=128, BK=64, 8 warps @ 32x64, ldmatrix.
__global__ void __launch_bounds__(NTHR, 1) k_xproj() {
    extern __shared__ __align__(16) char sm[];
    const int tid = threadIdx.x;
    const int lane = tid & 31;
    const int wid = tid >> 5;
    const int bx = blockIdx.x;  // m-tile
    const int by = blockIdx.y;  // n-tile

    const int mbase = (wid >> 1) * 32;
    const int nbase = (wid & 1) * 64;
    const int ra = lane >> 2;
    const int ca = (lane & 3) * 2;

    const __half* Asrc = d_Xh + (size_t)(bx * 128) * ND;
    const __half* Bsrc = d_Wx + (size_t)(by * 128) * ND;

    auto load = [&](int kc) {
        char* Ab = sm + (kc & 1) * XAB;
        char* Bb = sm + 2 * XAB + (kc & 1) * XAB;
#pragma unroll
        for (int j = 0; j < 4; ++j) {
            int q = tid + NTHR * j;
            int row = q >> 3;
            int seg = q & 7;
            cpasync16(sptr(Ab + (row * XSTR + seg * 8) * 2),
                      Asrc + (size_t)row * ND + kc * 64 + seg * 8);
        }
#pragma unroll
        for (int j = 0; j < 4; ++j) {
            int q = tid + NTHR * j;
            int row = q >> 3;
            int seg = q & 7;
            cpasync16(sptr(Bb + (row * XSTR + seg * 8) * 2),
                      Bsrc + (size_t)row * ND + kc * 64 + seg * 8);
        }
        cpcommit();
    };

    float acc[2][8][4];
#pragma unroll
    for (int mi = 0; mi < 2; ++mi)
#pragma unroll
        for (int n8 = 0; n8 < 8; ++n8)
#pragma unroll
            for (int t = 0; t < 4; ++t) acc[mi][n8][t] = 0.f;

    const int lr = (lane & 7) + ((lane >> 3) & 1) * 8;
    const int lc = (lane >> 4) * 8;

    load(0);
#pragma unroll 1
    for (int kc = 0; kc < 8; ++kc) {
        if (kc < 7) load(kc + 1);
        if (kc < 7) cpwait1();
        else cpwait0();
        __syncthreads();
        const unsigned Abs = sptr(sm + (kc & 1) * XAB);
        const unsigned Bbs = sptr(sm + 2 * XAB + (kc & 1) * XAB);
#pragma unroll
        for (int k16 = 0; k16 < 4; ++k16) {
            unsigned a[2][4];
#pragma unroll
            for (int mi = 0; mi < 2; ++mi) {
                unsigned addr =
                    Abs + (unsigned)(((mbase + mi * 16 + lr) * XSTR + k16 * 16 + lc) * 2);
                ldsm4(a[mi][0], a[mi][1], a[mi][2], a[mi][3], addr);
            }
#pragma unroll
            for (int np = 0; np < 4; ++np) {
                unsigned r0, r1, r2, r3;
                unsigned addr =
                    Bbs + (unsigned)(((nbase + np * 16 + lr) * XSTR + k16 * 16 + lc) * 2);
                ldsm4(r0, r1, r2, r3, addr);
#pragma unroll
                for (int mi = 0; mi < 2; ++mi) {
                    mma16816(acc[mi][2 * np], a[mi][0], a[mi][1], a[mi][2], a[mi][3], r0, r2);
                    mma16816(acc[mi][2 * np + 1], a[mi][0], a[mi][1], a[mi][2], a[mi][3], r1, r3);
                }
            }
        }
        __syncthreads();
    }

#pragma unroll
    for (int mi = 0; mi < 2; ++mi) {
#pragma unroll
        for (int n8 = 0; n8 < 8; ++n8) {
            int m0 = bx * 128 + mbase + mi * 16 + ra;
            int c0 = by * 128 + nbase + n8 * 8 + ca;
            *(__half2*)(d_XP + (size_t)m0 * NGP + c0) =
                __floats2half2_rn(acc[mi][n8][0], acc[mi][n8][1]);
            *(__half2*)(d_XP + (size_t)(m0 + 8) * NGP + c0) =
                __floats2half2_rn(acc[mi][n8][2], acc[mi][n8][3]);
        }
    }
}

// ---------------- persistent LSTM recurrence (R9 body + slice sync) ----------
// 128 CTAs x 256 thr. CTA owns 32 packed cols (8 hidden units). K=1024.
// Warp kq (0..7) computes 64M x 32N over K slice [kq*128, kq*128+128).
// Slice kq of H_s is produced by CTAs kq*16..kq*16+15; per-(s, kq) counters.
__global__ void __launch_bounds__(NTHR, 1) lstm_main(const float* __restrict__ C0,
                                                     float* __restrict__ out) {
    extern __shared__ __align__(16) char sm[];
    const int tid = threadIdx.x;
    const int lane = tid & 31;
    const int wid = tid >> 5;  // = kq
    const int cta = blockIdx.x;
    const int pbase = cta * 32;
    const int hbase = cta * 8;
    const int ra = lane >> 2;
    const int ca = (lane & 3) * 2;

    // ---- B fragments (once): 64 regs/thread ----
    unsigned Bf[4][8][2];
#pragma unroll
    for (int n8 = 0; n8 < 4; ++n8) {
        const __half* wp = d_Wh + (size_t)(pbase + n8 * 8 + ra) * NH + wid * 128 + ca;
#pragma unroll
        for (int k16 = 0; k16 < 8; ++k16) {
            Bf[n8][k16][0] = *(const unsigned*)(wp + k16 * 16);
            Bf[n8][k16][1] = *(const unsigned*)(wp + k16 * 16 + 8);
        }
    }

    // ---- gate-thread identity: (b, 2 hidden units) ----
    const int gb = tid & 63;
    const int gh2 = (tid >> 6) * 2;
    float bias8[8];
#pragma unroll
    for (int j = 0; j < 8; ++j) bias8[j] = d_bias[pbase + gh2 * 4 + j];
    float Creg0 = C0[(size_t)gb * NH + hbase + gh2];
    float Creg1 = C0[(size_t)gb * NH + hbase + gh2 + 1];

    // gather offsets (R9-proven mapping)
    int sl[8], gi_[8];
#pragma unroll
    for (int j = 0; j < 8; ++j) {
        int n = gh2 * 4 + j;
        sl[j] = (gb & 7) * 4 + ((n >> 1) & 3);
        gi_[j] = ((gb >> 4) * 4 + (n >> 3)) * 4 + ((gb >> 3) & 1) * 2 + (n & 1);
    }

    char* mych = sm + wid * CHB;
    const unsigned chs = sptr(mych);
    float* Pbuf = (float*)(sm + OFF_P);
    float* pw = Pbuf + wid * PWFL + lane * PWSTR;

    float* outHf = out + (size_t)NB * NS;
    float* outCf = outHf + (size_t)NB * NH;

    const unsigned grp = (unsigned)(cta >> 4);
    // per-thread XP source (fixed except for s) and smem slot
    const __half* xpsrc = d_XP + (size_t)gb * NGP + pbase + gh2 * 4;
    const unsigned xpsm = sptr(sm + OFF_XP) + (unsigned)(tid * 16);

    for (int s = 0; s < NS; ++s) {
        // ---- XP prefetch into smem (independent of H), group #1 ----
        const unsigned xslot = xpsm + (unsigned)((s & 1) * 4096);
        cpasync16(xslot, xpsrc + (size_t)s * NB * NGP);
        cpcommit();

        // ---- wait for the 16 producers of this warp's K-slice ----
        if (s > 0) {
            const unsigned* cp = &d_cnt[(size_t)s * 8 + wid];
            unsigned v;
            do {
                asm volatile("ld.acquire.gpu.global.u32 %0, [%1];" : "=r"(v) : "l"(cp));
            } while (v < 16u);
            __syncwarp();
        }

        // ---- per-warp load: 64 rows x 128 halves of H_s slice, 2 groups ----
        const __half* src = d_Hst + (size_t)s * NB * NH + wid * 128;
#pragma unroll
        for (int j = 0; j < 16; ++j) {
            int q = j * 32 + lane;
            int row = q >> 4;
            int seg = q & 15;
            cpasync16(chs + (unsigned)((row * CHSTR + seg * 8) * 2),
                      src + (size_t)row * NH + seg * 8);
        }
        cpcommit();
#pragma unroll
        for (int j = 16; j < 32; ++j) {
            int q = j * 32 + lane;
            int row = q >> 4;
            int seg = q & 15;
            cpasync16(chs + (unsigned)((row * CHSTR + seg * 8) * 2),
                      src + (size_t)row * NH + seg * 8);
        }
        cpcommit();

        float acc[4][4][4];
#pragma unroll
        for (int mi = 0; mi < 4; ++mi)
#pragma unroll
            for (int n8 = 0; n8 < 4; ++n8)
#pragma unroll
                for (int t = 0; t < 4; ++t) acc[mi][n8][t] = 0.f;

        cpwait1();  // XP + rows 0..31 ready
        const __half* Ab = (const __half*)mych;
#pragma unroll
        for (int k16 = 0; k16 < 8; ++k16) {
            const int k = k16 * 16;
            unsigned a[4][4];
#pragma unroll
            for (int mi = 0; mi < 4; ++mi) {
                if (mi < 2) {
                    int base = (mi * 16 + ra) * CHSTR + k + ca;
                    a[mi][0] = *(const unsigned*)(Ab + base);
                    a[mi][1] = *(const unsigned*)(Ab + base + 8 * CHSTR);
                    a[mi][2] = *(const unsigned*)(Ab + base + 8);
                    a[mi][3] = *(const unsigned*)(Ab + base + 8 * CHSTR + 8);
                }
            }
#pragma unroll
            for (int mi = 0; mi < 2; ++mi)
#pragma unroll
                for (int n8 = 0; n8 < 4; ++n8)
                    mma16816(acc[mi][n8], a[mi][0], a[mi][1], a[mi][2], a[mi][3],
                             Bf[n8][k16][0], Bf[n8][k16][1]);
        }
        cpwait0();  // rows 32..63 ready
#pragma unroll
        for (int k16 = 0; k16 < 8; ++k16) {
            const int k = k16 * 16;
            unsigned a[2][4];
#pragma unroll
            for (int mi = 0; mi < 2; ++mi) {
                int base = ((mi + 2) * 16 + ra) * CHSTR + k + ca;
                a[mi][0] = *(const unsigned*)(Ab + base);
                a[mi][1] = *(const unsigned*)(Ab + base + 8 * CHSTR);
                a[mi][2] = *(const unsigned*)(Ab + base + 8);
                a[mi][3] = *(const unsigned*)(Ab + base + 8 * CHSTR + 8);
            }
#pragma unroll
            for (int mi = 0; mi < 2; ++mi)
#pragma unroll
                for (int n8 = 0; n8 < 4; ++n8)
                    mma16816(acc[mi + 2][n8], a[mi][0], a[mi][1], a[mi][2], a[mi][3],
                             Bf[n8][k16][0], Bf[n8][k16][1]);
        }

        // ---- write partials ----
#pragma unroll
        for (int mi = 0; mi < 4; ++mi)
#pragma unroll
            for (int n8 = 0; n8 < 4; ++n8)
#pragma unroll
                for (int t = 0; t < 4; ++t)
                    pw[(mi * 4 + n8) * 4 + t] = acc[mi][n8][t];
        __syncthreads();

        // ---- 8-way K reduction + x_proj + gates ----
        {
            float g[8];
#pragma unroll
            for (int j = 0; j < 8; ++j) {
                float v = 0.f;
                const int off = sl[j] * PWSTR + gi_[j];
#pragma unroll
                for (int w = 0; w < 8; ++w) v += Pbuf[w * PWFL + off];
                g[j] = v;
            }
            uint4 xr;
            asm volatile("ld.shared.v4.u32 {%0,%1,%2,%3}, [%4];"
                         : "=r"(xr.x), "=r"(xr.y), "=r"(xr.z), "=r"(xr.w)
                         : "r"(xslot));
            const __half2* xh = (const __half2*)&xr;
            float xv[8];
#pragma unroll
            for (int t = 0; t < 4; ++t) {
                xv[2 * t] = __low2float(xh[t]);
                xv[2 * t + 1] = __high2float(xh[t]);
            }
            float hn0, hn1, cn0, cn1;
            {
                float gi = g[0] + bias8[0] + xv[0];
                float gf = g[1] + bias8[1] + xv[1];
                float go = g[2] + bias8[2] + xv[2];
                float gc = g[3] + bias8[3] + xv[3];
                float iv = sigmoidf_(gi), fv = sigmoidf_(gf);
                float ov = sigmoidf_(go), cv = tanhf(gc);
                cn0 = fv * Creg0 + iv * cv;
                hn0 = ov * tanhf(cn0);
                Creg0 = cn0;
            }
            {
                float gi = g[4] + bias8[4] + xv[4];
                float gf = g[5] + bias8[5] + xv[5];
                float go = g[6] + bias8[6] + xv[6];
                float gc = g[7] + bias8[7] + xv[7];
                float iv = sigmoidf_(gi), fv = sigmoidf_(gf);
                float ov = sigmoidf_(go), cv = tanhf(gc);
                cn1 = fv * Creg1 + iv * cv;
                hn1 = ov * tanhf(cn1);
                Creg1 = cn1;
            }
            *(__half2*)(d_Hst + (size_t)(s + 1) * NB * NH + (size_t)gb * NH + hbase + gh2) =
                __floats2half2_rn(hn0, hn1);
            if (s == NS - 1) {
                outHf[(size_t)gb * NH + hbase + gh2] = hn0;
                outHf[(size_t)gb * NH + hbase + gh2 + 1] = hn1;
                outCf[(size_t)gb * NH + hbase + gh2] = cn0;
                outCf[(size_t)gb * NH + hbase + gh2 + 1] = cn1;
            }
        }

        // ---- publish H_{s+1}: fence all threads' stores, then release-inc ----
        __threadfence();
        __syncthreads();
        if (tid == 0 && s < NS - 1) {
            const unsigned* cp = &d_cnt[(size_t)(s + 1) * 8 + grp];
            asm volatile("red.release.gpu.global.add.u32 [%0], %1;" ::"l"(cp), "r"(1u));
        }
    }
}

// ---------------- final GEMV: pred[b][s] ----------------
__global__ void k_pred(const float* __restrict__ fcW, const float* __restrict__ fcb,
                       float* __restrict__ out) {
    const int w = blockIdx.x * (blockDim.x >> 5) + (threadIdx.x >> 5);
    const int lane = threadIdx.x & 31;
    const int b = w >> 9;
    const int s = w & 511;
    const __half2* hp = (const __half2*)(d_Hst + (size_t)(s + 1) * NB * NH + (size_t)b * NH);
    const float2* wp = (const float2*)fcW;
    float acc = 0.f;
#pragma unroll 4
    for (int j = lane; j < NH / 2; j += 32) {
        __half2 h2 = hp[j];
        float2 wv = wp[j];
        acc += __low2float(h2) * wv.x + __high2float(h2) * wv.y;
    }
#pragma unroll
    for (int o = 16; o; o >>= 1) acc += __shfl_xor_sync(0xffffffffu, acc, o);
    if (lane == 0) out[(size_t)b * NS + s] = acc + fcb[0];
}

// ---------------- launch ----------------
extern "C" void kernel_launch(void* const* d_in, const int* in_sizes, int n_in,
                              void* d_out, int out_size) {
    (void)in_sizes;
    (void)n_in;
    (void)out_size;
    const float* x = (const float*)d_in[0];
    const float* H0 = (const float*)d_in[1];
    const float* C0 = (const float*)d_in[2];
    const float* Wxi = (const float*)d_in[3];
    const float* Whi = (const float*)d_in[4];
    const float* bi = (const float*)d_in[5];
    const float* Wxf = (const float*)d_in[6];
    const float* Whf = (const float*)d_in[7];
    const float* bf_ = (const float*)d_in[8];
    const float* Wxo = (const float*)d_in[9];
    const float* Who = (const float*)d_in[10];
    const float* bo = (const float*)d_in[11];
    const float* Wxc = (const float*)d_in[12];
    const float* Whc = (const float*)d_in[13];
    const float* bc = (const float*)d_in[14];
    const float* fcW = (const float*)d_in[15];
    const float* fcb = (const float*)d_in[16];
    float* out = (float*)d_out;

    cudaFuncSetAttribute(lstm_main, cudaFuncAttributeMaxDynamicSharedMemorySize, SMEM_MAIN);
    cudaFuncSetAttribute(k_xproj, cudaFuncAttributeMaxDynamicSharedMemorySize, SMEM_XP);

    k_pack<<<2048, 256>>>(Wxi, Whi, bi, Wxf, Whf, bf_, Wxo, Who, bo, Wxc, Whc, bc);
    k_prep<<<4096, 256>>>(x, H0);
    {
        dim3 g(256, 32);
        k_xproj<<<g, NTHR, SMEM_XP>>>();
    }
    lstm_main<<<NCTA, NTHR, SMEM_MAIN>>>(C0, out);
    k_pred<<<4096, 256>>>(fcW, fcb, out);
}

// round 17
// speedup vs baseline: 1.8447x; 1.0393x over previous
#include <cuda_runtime.h>
#include <cuda_fp16.h>
#include <cstdint>

// ---------------- problem dims ----------------
#define NB 64      // batch
#define ND 512     // input dim
#define NH 1024    // hidden
#define NS 512     // seq len
#define NGP 4096   // packed gate columns (4*H)
#define NCTA 128
#define NTHR 256

// ---------------- lstm_main smem layout ----------------
#define CHSTR 136                        // halves per A row (128 + 8 pad)
#define CHB (64 * CHSTR * 2)             // 17408 bytes per warp chunk
#define OFF_P (8 * CHB)                  // 139264
#define PWSTR 65                         // floats per lane slot (64 idx + pad)
#define PWFL (32 * PWSTR)                // 2080 floats per warp partial buf
#define OFF_XP (OFF_P + 8 * PWFL * 4)    // 205824
#define SMEM_MAIN (OFF_XP + 2 * 4096)    // + double-buffered XP slab = 214016

// ---------------- xproj smem layout ----------------
#define XSTR 72                          // halves per row (64 + 8 pad)
#define XAB (128 * XSTR * 2)             // 18432 per buffer
#define SMEM_XP (4 * XAB)                // 73728: A0,A1,B0,B1

// ---------------- device scratch (static; no runtime alloc) ----------------
__device__ __half d_Wh[(size_t)NGP * NH];            // packed Wh [p][k]
__device__ __half d_Wx[(size_t)NGP * ND];            // packed Wx [p][k]
__device__ float d_bias[NGP];
__device__ __half d_Xh[(size_t)NS * NB * ND];        // x [s][b][d] fp16
__device__ __half d_XP[(size_t)NS * NB * NGP];       // x_proj [s*64+b][p] fp16
__device__ __half d_Hst[(size_t)(NS + 1) * NB * NH]; // H history [t][b][h]
__device__ unsigned d_cnt[NS * 8];                   // per-(step, slice) counters

// ---------------- helpers ----------------
static __device__ __forceinline__ unsigned sptr(const void* p) {
    return (unsigned)__cvta_generic_to_shared(p);
}
static __device__ __forceinline__ void cpasync16(unsigned dst, const void* src) {
    asm volatile("cp.async.cg.shared.global [%0], [%1], 16;" ::"r"(dst), "l"(src));
}
static __device__ __forceinline__ void cpcommit() {
    asm volatile("cp.async.commit_group;");
}
static __device__ __forceinline__ void cpwait0() {
    asm volatile("cp.async.wait_group 0;");
}
static __device__ __forceinline__ void cpwait1() {
    asm volatile("cp.async.wait_group 1;");
}
static __device__ __forceinline__ void ldsm4(unsigned& r0, unsigned& r1, unsigned& r2,
                                             unsigned& r3, unsigned addr) {
    asm volatile("ldmatrix.sync.aligned.m8n8.x4.shared.b16 {%0,%1,%2,%3}, [%4];"
                 : "=r"(r0), "=r"(r1), "=r"(r2), "=r"(r3)
                 : "r"(addr));
}
static __device__ __forceinline__ void mma16816(float* d, unsigned a0, unsigned a1,
                                                unsigned a2, unsigned a3,
                                                unsigned b0, unsigned b1) {
    asm volatile(
        "mma.sync.aligned.m16n8k16.row.col.f32.f16.f16.f32 "
        "{%0,%1,%2,%3}, {%4,%5,%6,%7}, {%8,%9}, {%0,%1,%2,%3};"
        : "+f"(d[0]), "+f"(d[1]), "+f"(d[2]), "+f"(d[3])
        : "r"(a0), "r"(a1), "r"(a2), "r"(a3), "r"(b0), "r"(b1));
}
static __device__ __forceinline__ float sigmoidf_(float x) {
    return 1.0f / (1.0f + __expf(-x));
}
static __device__ __forceinline__ float tanhf_(float x) {
    float y;
    asm("tanh.approx.f32 %0, %1;" : "=f"(y) : "f"(x));
    return y;
}
// partial-buffer index permutation: moves the lane-varying idx bits (b1, b4)
// into bank positions 0,1 so bank = 4*(lane&7) + b3 + 2*b4 is a lane bijection
// -> conflict-free STS writes AND gather reads. Compile-time on the write side.
static __device__ __forceinline__ int permi(int i) {
    return ((i >> 1) & 1) | (((i >> 4) & 1) << 1) | ((i & 1) << 2) |
           (((i >> 2) & 1) << 3) | (((i >> 3) & 1) << 4) | (i & 32);
}

// ---------------- pack weights (transpose to [p][k], fp16) + bias + cnt ------
__global__ void k_pack(const float* __restrict__ Wxi, const float* __restrict__ Whi,
                       const float* __restrict__ bi, const float* __restrict__ Wxf,
                       const float* __restrict__ Whf, const float* __restrict__ bf_,
                       const float* __restrict__ Wxo, const float* __restrict__ Who,
                       const float* __restrict__ bo, const float* __restrict__ Wxc,
                       const float* __restrict__ Whc, const float* __restrict__ bc) {
    const float* Wx[4] = {Wxi, Wxf, Wxo, Wxc};
    const float* Wh[4] = {Whi, Whf, Who, Whc};
    const float* bb[4] = {bi, bf_, bo, bc};
    size_t i = (size_t)blockIdx.x * blockDim.x + threadIdx.x;
    size_t stride = (size_t)gridDim.x * blockDim.x;
    for (size_t idx = i; idx < (size_t)NS * 8; idx += stride) d_cnt[idx] = 0u;
    for (size_t idx = i; idx < (size_t)NGP * NH; idx += stride) {
        int k = (int)(idx % NH);
        int p = (int)(idx / NH);
        d_Wh[idx] = __float2half(Wh[p & 3][(size_t)k * NH + (p >> 2)]);
    }
    for (size_t idx = i; idx < (size_t)NGP * ND; idx += stride) {
        int k = (int)(idx % ND);
        int p = (int)(idx / ND);
        d_Wx[idx] = __float2half(Wx[p & 3][(size_t)k * NH + (p >> 2)]);
    }
    for (size_t idx = i; idx < (size_t)NGP; idx += stride) {
        d_bias[idx] = bb[idx & 3][idx >> 2];
    }
}

// ---------------- prep: x -> [s][b][d] fp16; H0 -> Hst[0] --------------------
__global__ void k_prep(const float* __restrict__ x, const float* __restrict__ H0) {
    size_t i = (size_t)blockIdx.x * blockDim.x + threadIdx.x;
    size_t stride = (size_t)gridDim.x * blockDim.x;
    for (size_t idx = i; idx < (size_t)NS * NB * ND; idx += stride) {
        size_t d = idx % ND;
        size_t sb = idx / ND;
        size_t b = sb % NB;
        size_t s = sb / NB;
        d_Xh[idx] = __float2half(x[(b * NS + s) * ND + d]);
    }
    for (size_t idx = i; idx < (size_t)NB * NH; idx += stride) {
        d_Hst[idx] = __float2half(H0[idx]);
    }
}

// ---------------- xproj GEMM: XP[m][p] = sum_d Xh[m][d] * Wx[p][d] -----------
// M=32768, N=4096, K=512. BM=128, BN=128, BK=64, 8 warps @ 32x64, ldmatrix.
__global__ void __launch_bounds__(NTHR, 1) k_xproj() {
    extern __shared__ __align__(16) char sm[];
    const int tid = threadIdx.x;
    const int lane = tid & 31;
    const int wid = tid >> 5;
    const int bx = blockIdx.x;  // m-tile
    const int by = blockIdx.y;  // n-tile

    const int mbase = (wid >> 1) * 32;
    const int nbase = (wid & 1) * 64;
    const int ra = lane >> 2;
    const int ca = (lane & 3) * 2;

    const __half* Asrc = d_Xh + (size_t)(bx * 128) * ND;
    const __half* Bsrc = d_Wx + (size_t)(by * 128) * ND;

    auto load = [&](int kc) {
        char* Ab = sm + (kc & 1) * XAB;
        char* Bb = sm + 2 * XAB + (kc & 1) * XAB;
#pragma unroll
        for (int j = 0; j < 4; ++j) {
            int q = tid + NTHR * j;
            int row = q >> 3;
            int seg = q & 7;
            cpasync16(sptr(Ab + (row * XSTR + seg * 8) * 2),
                      Asrc + (size_t)row * ND + kc * 64 + seg * 8);
        }
#pragma unroll
        for (int j = 0; j < 4; ++j) {
            int q = tid + NTHR * j;
            int row = q >> 3;
            int seg = q & 7;
            cpasync16(sptr(Bb + (row * XSTR + seg * 8) * 2),
                      Bsrc + (size_t)row * ND + kc * 64 + seg * 8);
        }
        cpcommit();
    };

    float acc[2][8][4];
#pragma unroll
    for (int mi = 0; mi < 2; ++mi)
#pragma unroll
        for (int n8 = 0; n8 < 8; ++n8)
#pragma unroll
            for (int t = 0; t < 4; ++t) acc[mi][n8][t] = 0.f;

    const int lr = lane & 15;
    const int lc = (lane >> 4) * 8;

    load(0);
#pragma unroll 1
    for (int kc = 0; kc < 8; ++kc) {
        if (kc < 7) load(kc + 1);
        if (kc < 7) cpwait1();
        else cpwait0();
        __syncthreads();
        const unsigned Abs = sptr(sm + (kc & 1) * XAB);
        const unsigned Bbs = sptr(sm + 2 * XAB + (kc & 1) * XAB);
#pragma unroll
        for (int k16 = 0; k16 < 4; ++k16) {
            unsigned a[2][4];
#pragma unroll
            for (int mi = 0; mi < 2; ++mi) {
                unsigned addr =
                    Abs + (unsigned)(((mbase + mi * 16 + lr) * XSTR + k16 * 16 + lc) * 2);
                ldsm4(a[mi][0], a[mi][1], a[mi][2], a[mi][3], addr);
            }
#pragma unroll
            for (int np = 0; np < 4; ++np) {
                unsigned r0, r1, r2, r3;
                unsigned addr =
                    Bbs + (unsigned)(((nbase + np * 16 + lr) * XSTR + k16 * 16 + lc) * 2);
                ldsm4(r0, r1, r2, r3, addr);
#pragma unroll
                for (int mi = 0; mi < 2; ++mi) {
                    mma16816(acc[mi][2 * np], a[mi][0], a[mi][1], a[mi][2], a[mi][3], r0, r2);
                    mma16816(acc[mi][2 * np + 1], a[mi][0], a[mi][1], a[mi][2], a[mi][3], r1, r3);
                }
            }
        }
        __syncthreads();
    }

#pragma unroll
    for (int mi = 0; mi < 2; ++mi) {
#pragma unroll
        for (int n8 = 0; n8 < 8; ++n8) {
            int m0 = bx * 128 + mbase + mi * 16 + ra;
            int c0 = by * 128 + nbase + n8 * 8 + ca;
            *(__half2*)(d_XP + (size_t)m0 * NGP + c0) =
                __floats2half2_rn(acc[mi][n8][0], acc[mi][n8][1]);
            *(__half2*)(d_XP + (size_t)(m0 + 8) * NGP + c0) =
                __floats2half2_rn(acc[mi][n8][2], acc[mi][n8][3]);
        }
    }
}

// ---------------- persistent LSTM recurrence (slice-synced, ldmatrix) --------
// 128 CTAs x 256 thr. CTA owns 32 packed cols (8 hidden units). K=1024.
// Warp kq (0..7) computes 64M x 32N over K slice [kq*128, kq*128+128).
// Slice kq of H_s is produced by CTAs kq*16..kq*16+15; per-(s, kq) counters.
__global__ void __launch_bounds__(NTHR, 1) lstm_main(const float* __restrict__ C0,
                                                     float* __restrict__ out) {
    extern __shared__ __align__(16) char sm[];
    const int tid = threadIdx.x;
    const int lane = tid & 31;
    const int wid = tid >> 5;  // = kq
    const int cta = blockIdx.x;
    const int pbase = cta * 32;
    const int hbase = cta * 8;
    const int ra = lane >> 2;
    const int ca = (lane & 3) * 2;

    // ---- B fragments (once): 64 regs/thread ----
    unsigned Bf[4][8][2];
#pragma unroll
    for (int n8 = 0; n8 < 4; ++n8) {
        const __half* wp = d_Wh + (size_t)(pbase + n8 * 8 + ra) * NH + wid * 128 + ca;
#pragma unroll
        for (int k16 = 0; k16 < 8; ++k16) {
            Bf[n8][k16][0] = *(const unsigned*)(wp + k16 * 16);
            Bf[n8][k16][1] = *(const unsigned*)(wp + k16 * 16 + 8);
        }
    }

    // ---- gate-thread identity: (b, 2 hidden units) ----
    const int gb = tid & 63;
    const int gh2 = (tid >> 6) * 2;
    float bias8[8];
#pragma unroll
    for (int j = 0; j < 8; ++j) bias8[j] = d_bias[pbase + gh2 * 4 + j];
    float Creg0 = C0[(size_t)gb * NH + hbase + gh2];
    float Creg1 = C0[(size_t)gb * NH + hbase + gh2 + 1];

    // gather offsets (permuted idx -> conflict-free)
    int sl[8], gi_[8];
#pragma unroll
    for (int j = 0; j < 8; ++j) {
        int n = gh2 * 4 + j;
        sl[j] = (gb & 7) * 4 + ((n >> 1) & 3);
        gi_[j] = permi(((gb >> 4) * 4 + (n >> 3)) * 4 + ((gb >> 3) & 1) * 2 + (n & 1));
    }

    char* mych = sm + wid * CHB;
    const unsigned chs = sptr(mych);
    float* Pbuf = (float*)(sm + OFF_P);
    float* pw = Pbuf + wid * PWFL + lane * PWSTR;

    // ldmatrix lane statics for A chunk (mapping proven in R11)
    const unsigned abase = chs + (unsigned)(((lane & 15) * CHSTR + (lane >> 4) * 8) * 2);

    float* outHf = out + (size_t)NB * NS;
    float* outCf = outHf + (size_t)NB * NH;

    const unsigned grp = (unsigned)(cta >> 4);
    const __half* xpsrc = d_XP + (size_t)gb * NGP + pbase + gh2 * 4;
    const unsigned xpsm = sptr(sm + OFF_XP) + (unsigned)(tid * 16);

    for (int s = 0; s < NS; ++s) {
        // ---- XP prefetch into smem (independent of H), group #1 ----
        const unsigned xslot = xpsm + (unsigned)((s & 1) * 4096);
        cpasync16(xslot, xpsrc + (size_t)s * NB * NGP);
        cpcommit();

        // ---- wait for the 16 producers of this warp's K-slice ----
        if (s > 0) {
            const unsigned* cp = &d_cnt[(size_t)s * 8 + wid];
            unsigned v;
            do {
                asm volatile("ld.acquire.gpu.global.u32 %0, [%1];" : "=r"(v) : "l"(cp));
            } while (v < 16u);
            __syncwarp();
        }

        // ---- per-warp load: 64 rows x 128 halves of H_s slice, 2 groups ----
        const __half* src = d_Hst + (size_t)s * NB * NH + wid * 128;
#pragma unroll
        for (int j = 0; j < 16; ++j) {
            int q = j * 32 + lane;
            int row = q >> 4;
            int seg = q & 15;
            cpasync16(chs + (unsigned)((row * CHSTR + seg * 8) * 2),
                      src + (size_t)row * NH + seg * 8);
        }
        cpcommit();
#pragma unroll
        for (int j = 16; j < 32; ++j) {
            int q = j * 32 + lane;
            int row = q >> 4;
            int seg = q & 15;
            cpasync16(chs + (unsigned)((row * CHSTR + seg * 8) * 2),
                      src + (size_t)row * NH + seg * 8);
        }
        cpcommit();

        float acc[4][4][4];
#pragma unroll
        for (int mi = 0; mi < 4; ++mi)
#pragma unroll
            for (int n8 = 0; n8 < 4; ++n8)
#pragma unroll
                for (int t = 0; t < 4; ++t) acc[mi][n8][t] = 0.f;

        cpwait1();  // XP + rows 0..31 ready
#pragma unroll
        for (int mi = 0; mi < 2; ++mi)
#pragma unroll
            for (int k16 = 0; k16 < 8; ++k16) {
                unsigned a0, a1, a2, a3;
                ldsm4(a0, a1, a2, a3,
                      abase + (unsigned)(mi * 16 * CHSTR * 2 + k16 * 32));
#pragma unroll
                for (int n8 = 0; n8 < 4; ++n8)
                    mma16816(acc[mi][n8], a0, a1, a2, a3, Bf[n8][k16][0], Bf[n8][k16][1]);
            }
        cpwait0();  // rows 32..63 ready
#pragma unroll
        for (int mi = 2; mi < 4; ++mi)
#pragma unroll
            for (int k16 = 0; k16 < 8; ++k16) {
                unsigned a0, a1, a2, a3;
                ldsm4(a0, a1, a2, a3,
                      abase + (unsigned)(mi * 16 * CHSTR * 2 + k16 * 32));
#pragma unroll
                for (int n8 = 0; n8 < 4; ++n8)
                    mma16816(acc[mi][n8], a0, a1, a2, a3, Bf[n8][k16][0], Bf[n8][k16][1]);
            }

        // ---- write partials (permuted idx: conflict-free) ----
#pragma unroll
        for (int mi = 0; mi < 4; ++mi)
#pragma unroll
            for (int n8 = 0; n8 < 4; ++n8)
#pragma unroll
                for (int t = 0; t < 4; ++t)
                    pw[permi((mi * 4 + n8) * 4 + t)] = acc[mi][n8][t];
        __syncthreads();

        // ---- 8-way K reduction + x_proj + gates ----
        {
            float g[8];
#pragma unroll
            for (int j = 0; j < 8; ++j) {
                float v = 0.f;
                const int off = sl[j] * PWSTR + gi_[j];
#pragma unroll
                for (int w = 0; w < 8; ++w) v += Pbuf[w * PWFL + off];
                g[j] = v;
            }
            uint4 xr;
            asm volatile("ld.shared.v4.u32 {%0,%1,%2,%3}, [%4];"
                         : "=r"(xr.x), "=r"(xr.y), "=r"(xr.z), "=r"(xr.w)
                         : "r"(xslot));
            const __half2* xh = (const __half2*)&xr;
            float xv[8];
#pragma unroll
            for (int t = 0; t < 4; ++t) {
                xv[2 * t] = __low2float(xh[t]);
                xv[2 * t + 1] = __high2float(xh[t]);
            }
            float hn0, hn1, cn0, cn1;
            {
                float gi = g[0] + bias8[0] + xv[0];
                float gf = g[1] + bias8[1] + xv[1];
                float go = g[2] + bias8[2] + xv[2];
                float gc = g[3] + bias8[3] + xv[3];
                float iv = sigmoidf_(gi), fv = sigmoidf_(gf);
                float ov = sigmoidf_(go), cv = tanhf_(gc);
                cn0 = fv * Creg0 + iv * cv;
                hn0 = ov * tanhf_(cn0);
                Creg0 = cn0;
            }
            {
                float gi = g[4] + bias8[4] + xv[4];
                float gf = g[5] + bias8[5] + xv[5];
                float go = g[6] + bias8[6] + xv[6];
                float gc = g[7] + bias8[7] + xv[7];
                float iv = sigmoidf_(gi), fv = sigmoidf_(gf);
                float ov = sigmoidf_(go), cv = tanhf_(gc);
                cn1 = fv * Creg1 + iv * cv;
                hn1 = ov * tanhf_(cn1);
                Creg1 = cn1;
            }
            *(__half2*)(d_Hst + (size_t)(s + 1) * NB * NH + (size_t)gb * NH + hbase + gh2) =
                __floats2half2_rn(hn0, hn1);
            if (s == NS - 1) {
                outHf[(size_t)gb * NH + hbase + gh2] = hn0;
                outHf[(size_t)gb * NH + hbase + gh2 + 1] = hn1;
                outCf[(size_t)gb * NH + hbase + gh2] = cn0;
                outCf[(size_t)gb * NH + hbase + gh2 + 1] = cn1;
            }
        }

        // ---- publish H_{s+1}: fence all threads' stores, then release-inc ----
        __threadfence();
        __syncthreads();
        if (tid == 0 && s < NS - 1) {
            const unsigned* cp = &d_cnt[(size_t)(s + 1) * 8 + grp];
            asm volatile("red.release.gpu.global.add.u32 [%0], %1;" ::"l"(cp), "r"(1u));
        }
    }
}

// ---------------- final GEMV: pred[b][s] ----------------
__global__ void k_pred(const float* __restrict__ fcW, const float* __restrict__ fcb,
                       float* __restrict__ out) {
    const int w = blockIdx.x * (blockDim.x >> 5) + (threadIdx.x >> 5);
    const int lane = threadIdx.x & 31;
    const int b = w >> 9;
    const int s = w & 511;
    const __half2* hp = (const __half2*)(d_Hst + (size_t)(s + 1) * NB * NH + (size_t)b * NH);
    const float2* wp = (const float2*)fcW;
    float acc = 0.f;
#pragma unroll 4
    for (int j = lane; j < NH / 2; j += 32) {
        __half2 h2 = hp[j];
        float2 wv = wp[j];
        acc += __low2float(h2) * wv.x + __high2float(h2) * wv.y;
    }
#pragma unroll
    for (int o = 16; o; o >>= 1) acc += __shfl_xor_sync(0xffffffffu, acc, o);
    if (lane == 0) out[(size_t)b * NS + s] = acc + fcb[0];
}

// ---------------- launch ----------------
extern "C" void kernel_launch(void* const* d_in, const int* in_sizes, int n_in,
                              void* d_out, int out_size) {
    (void)in_sizes;
    (void)n_in;
    (void)out_size;
    const float* x = (const float*)d_in[0];
    const float* H0 = (const float*)d_in[1];
    const float* C0 = (const float*)d_in[2];
    const float* Wxi = (const float*)d_in[3];
    const float* Whi = (const float*)d_in[4];
    const float* bi = (const float*)d_in[5];
    const float* Wxf = (const float*)d_in[6];
    const float* Whf = (const float*)d_in[7];
    const float* bf_ = (const float*)d_in[8];
    const float* Wxo = (const float*)d_in[9];
    const float* Who = (const float*)d_in[10];
    const float* bo = (const float*)d_in[11];
    const float* Wxc = (const float*)d_in[12];
    const float* Whc = (const float*)d_in[13];
    const float* bc = (const float*)d_in[14];
    const float* fcW = (const float*)d_in[15];
    const float* fcb = (const float*)d_in[16];
    float* out = (float*)d_out;

    cudaFuncSetAttribute(lstm_main, cudaFuncAttributeMaxDynamicSharedMemorySize, SMEM_MAIN);
    cudaFuncSetAttribute(k_xproj, cudaFuncAttributeMaxDynamicSharedMemorySize, SMEM_XP);

    k_pack<<<2048, 256>>>(Wxi, Whi, bi, Wxf, Whf, bf_, Wxo, Who, bo, Wxc, Whc, bc);
    k_prep<<<4096, 256>>>(x, H0);
    {
        dim3 g(256, 32);
        k_xproj<<<g, NTHR, SMEM_XP>>>();
    }
    lstm_main<<<NCTA, NTHR, SMEM_MAIN>>>(C0, out);
    k_pred<<<4096, 256>>>(fcW, fcb, out);
}